// round 1
// baseline (speedup 1.0000x reference)
#include <cuda_runtime.h>
#include <cstdint>

// CostBuilder: stereo cost-volume construction.
// left, right: (B=4, C=32, H=64, W=128) fp32
// out:         (B, 2C=64, D=48, H, W) fp32
//   out[b, c,    d, h, w] = (w>=d) ? left [b,c,h,w]   : 0
//   out[b, C+c,  d, h, w] = (w>=d) ? right[b,c,h,w-d] : 0
//
// Pure HBM-store-bound (~403 MB out, 8 MB in). One block per (b,c,h) row pair;
// right row staged in shared, left row in registers; float4 stores.

namespace {
constexpr int B = 4;
constexpr int C = 32;
constexpr int H = 64;
constexpr int W = 128;
constexpr int D = 48;           // MAX_DISP / 4
constexpr int TPB = 256;        // 8 warps: lanes cover W/4, warps cover d strided
constexpr int WARPS = TPB / 32;
}

__global__ __launch_bounds__(TPB) void cost_builder_kernel(
    const float* __restrict__ left,
    const float* __restrict__ right,
    float* __restrict__ out)
{
    // blockIdx.x enumerates (b, c, h): bc = b*C + c
    const int bch = blockIdx.x;
    const int h   = bch % H;
    const int bc  = bch / H;          // b*C + c
    const int c   = bc % C;
    const int b   = bc / C;

    __shared__ float s_right[W];

    const float* lrow = left  + ((size_t)bc * H + h) * W;
    const float* rrow = right + ((size_t)bc * H + h) * W;

    const int tid   = threadIdx.x;
    const int lane4 = tid & 31;       // which group of 4 w's
    const int warp  = tid >> 5;       // d-group 0..7
    const int w0    = lane4 * 4;

    // Stage the right row into shared (32 float4 loads by warp 0).
    if (tid < W / 4) {
        reinterpret_cast<float4*>(s_right)[tid] =
            reinterpret_cast<const float4*>(rrow)[tid];
    }

    // Left values this lane owns, kept in registers across all d.
    const float4 lv = reinterpret_cast<const float4*>(lrow)[lane4];

    __syncthreads();

    // Output index: (((b*2C + ch) * D + d) * H + h) * W + w
    const size_t dL = (size_t)(b * 2 * C + c)     * D;   // left-part channel base (in D units)
    const size_t dR = (size_t)(b * 2 * C + C + c) * D;   // right-part channel base

    #pragma unroll
    for (int d = warp; d < D; d += WARPS) {
        float4 ov, rv;
        ov.x = (w0     >= d) ? lv.x : 0.0f;
        ov.y = (w0 + 1 >= d) ? lv.y : 0.0f;
        ov.z = (w0 + 2 >= d) ? lv.z : 0.0f;
        ov.w = (w0 + 3 >= d) ? lv.w : 0.0f;

        rv.x = (w0     >= d) ? s_right[w0     - d] : 0.0f;
        rv.y = (w0 + 1 >= d) ? s_right[w0 + 1 - d] : 0.0f;
        rv.z = (w0 + 2 >= d) ? s_right[w0 + 2 - d] : 0.0f;
        rv.w = (w0 + 3 >= d) ? s_right[w0 + 3 - d] : 0.0f;

        const size_t offL = ((dL + d) * H + h) * W + w0;
        const size_t offR = ((dR + d) * H + h) * W + w0;
        *reinterpret_cast<float4*>(out + offL) = ov;
        *reinterpret_cast<float4*>(out + offR) = rv;
    }
}

extern "C" void kernel_launch(void* const* d_in, const int* in_sizes, int n_in,
                              void* d_out, int out_size)
{
    const float* left  = (const float*)d_in[0];
    const float* right = (const float*)d_in[1];
    float* out = (float*)d_out;

    const int grid = B * C * H;   // 8192 blocks
    cost_builder_kernel<<<grid, TPB>>>(left, right, out);
}